// round 6
// baseline (speedup 1.0000x reference)
#include <cuda_runtime.h>

#define N 768
#define D 512
#define MAXP ((N * (N - 1)) / 2)
#define NB 768
#define NT 256
#define NWARP (NB * NT / 32)          // 6144 warps

// Scratch (no allocations allowed anywhere). Zero-initialized at load.
__device__ float  g_mu[N * D];
__device__ float  g_sig[N * D];
__device__ int    g_pairs[MAXP];
__device__ double g_part[NB];
__device__ int    g_cnt;              // pair count; reset by last-done block
__device__ int    g_arrive;           // grid barrier (ticketed, replay-safe)
__device__ int    g_done;

__device__ __forceinline__ float fast_rcp(float x) {
    float r; asm("rcp.approx.f32 %0, %1;" : "=f"(r) : "f"(x)); return r;
}
__device__ __forceinline__ float fast_lg2(float x) {
    float r; asm("lg2.approx.f32 %0, %1;" : "=f"(r) : "f"(x)); return r;
}

__global__ void __launch_bounds__(NT)
mls_fused(const float* __restrict__ muX,
          const float* __restrict__ lss,
          const void*  __restrict__ gty,
          float* __restrict__ out) {
    __shared__ float  ws[4];
    __shared__ double wsum[NT / 32];

    int t    = threadIdx.x;
    int lane = t & 31;
    int wid  = t >> 5;
    int row  = blockIdx.x;

    // ================= PHASE A: prep + pair generation ====================
    // Threads 0-127: normalize mu row. Threads 128-255: exp(sig) row.
    float4 v;
    if (t < 128) {
        v = ((const float4*)(muX + (size_t)row * D))[t];
        float ss = v.x * v.x + v.y * v.y + v.z * v.z + v.w * v.w;
        #pragma unroll
        for (int o = 16; o; o >>= 1) ss += __shfl_xor_sync(0xFFFFFFFFu, ss, o);
        if (lane == 0) ws[wid] = ss;
    } else {
        int ht = t - 128;
        float4 l = ((const float4*)(lss + (size_t)row * D))[ht];
        ((float4*)(g_sig + (size_t)row * D))[ht] =
            make_float4(__expf(l.x), __expf(l.y), __expf(l.z), __expf(l.w));
    }

    // Label width detection: gty values in [0,64). If little-endian int64,
    // every odd 32-bit word of the first N words is 0. Index 2*j <= 1534 is
    // in-bounds for the int64 layout; N words in-bounds for int32.
    const int* gw = (const int*)gty;
    int flag = 0;
    #pragma unroll
    for (int k = 0; k < 3; k++) {
        int x = t + (k << 8);
        if ((x & 1) && gw[x] != 0) flag = 1;
    }
    int is32 = __syncthreads_or(flag);

    if (t < 128) {
        float total = ws[0] + ws[1] + ws[2] + ws[3];
        float rn = 1.0f / fmaxf(sqrtf(total), 1e-12f);
        ((float4*)(g_mu + (size_t)row * D))[t] =
            make_float4(v.x * rn, v.y * rn, v.z * rn, v.w * rn);
    }

    // Pair generation for this block's row: scan j, keep j>row & same label
    int li = is32 ? gw[row] : gw[2 * row];
    #pragma unroll
    for (int k = 0; k < 3; k++) {
        int j = t + (k << 8);
        bool m = (j > row) && ((is32 ? gw[j] : gw[2 * j]) == li);
        unsigned bal = __ballot_sync(0xFFFFFFFFu, m);
        int cnt = __popc(bal);
        int base = 0;
        if (lane == 0 && cnt) base = atomicAdd(&g_cnt, cnt);
        base = __shfl_sync(0xFFFFFFFFu, base, 0);
        if (m) g_pairs[base + __popc(bal & ((1u << lane) - 1))] = (row << 16) | j;
    }

    // ================= grid barrier (replay-safe ticketed) ================
    if (t == 0) {
        __threadfence();                              // release phase-A writes
        int ticket = atomicAdd(&g_arrive, 1);
        int target = (ticket / NB + 1) * NB;
        volatile int* va = &g_arrive;
        while (*va < target) __nanosleep(32);
    }
    __syncthreads();
    __threadfence();   // acquire side: order phase-B loads after the barrier

    // ================= PHASE B: MLS over (pair, quarter) units ============
    int np = g_cnt;
    int nu = np << 2;
    int gwarp = blockIdx.x * (NT / 32) + wid;

    float accd = 0.0f, accl = 0.0f;
    for (int u = gwarp; u < nu; u += NWARP) {
        int pk = g_pairs[u >> 2];
        int pi = pk >> 16;
        int pj = pk & 0xFFFF;
        int f4 = ((u & 3) << 5) + lane;               // float4 index (0..127)
        float4 a  = ((const float4*)(g_mu  + (size_t)pi * D))[f4];
        float4 b  = ((const float4*)(g_mu  + (size_t)pj * D))[f4];
        float4 uu = ((const float4*)(g_sig + (size_t)pi * D))[f4];
        float4 vv = ((const float4*)(g_sig + (size_t)pj * D))[f4];
        float d, s, prod;
        d = a.x - b.x; s = uu.x + vv.x + 1e-10f;
        accd += d * d * fast_rcp(s); prod = s;
        d = a.y - b.y; s = uu.y + vv.y + 1e-10f;
        accd += d * d * fast_rcp(s); prod *= s;
        d = a.z - b.z; s = uu.z + vv.z + 1e-10f;
        accd += d * d * fast_rcp(s); prod *= s;
        d = a.w - b.w; s = uu.w + vv.w + 1e-10f;
        accd += d * d * fast_rcp(s); prod *= s;
        accl += fast_lg2(prod);                       // 1 lg2 per 4 elems
    }

    // warp reduce (float) then block reduce (double)
    float val = accd + 0.69314718055994531f * accl;
    #pragma unroll
    for (int o = 16; o; o >>= 1) val += __shfl_xor_sync(0xFFFFFFFFu, val, o);
    if (lane == 0) wsum[wid] = (double)val;
    __syncthreads();

    __shared__ int sh_last;
    if (t == 0) {
        double bs = 0.0;
        #pragma unroll
        for (int w = 0; w < NT / 32; w++) bs += wsum[w];
        g_part[blockIdx.x] = bs;
        __threadfence();
        sh_last = (atomicAdd(&g_done, 1) == NB - 1) ? 1 : 0;
    }
    __syncthreads();

    // last-done block: deterministic final reduction + counter resets
    if (sh_last) {
        double a2 = 0.0;
        #pragma unroll
        for (int k = 0; k < NB / NT; k++)
            a2 += __ldcg(&g_part[t + k * NT]);
        #pragma unroll
        for (int o = 16; o; o >>= 1) a2 += __shfl_xor_sync(0xFFFFFFFFu, a2, o);
        if (lane == 0) wsum[wid] = a2;
        __syncthreads();
        if (t == 0) {
            double s = 0.0;
            #pragma unroll
            for (int w = 0; w < NT / 32; w++) s += wsum[w];
            out[0] = np ? (float)(s / (double)np) : 0.0f;
            g_done = 0;                // reset for next graph replay
            g_cnt = 0;
            g_arrive = 0;              // all blocks are past the barrier here
        }
    }
}

extern "C" void kernel_launch(void* const* d_in, const int* in_sizes, int n_in,
                              void* d_out, int out_size) {
    const float* muX = (const float*)d_in[0];
    const float* lss = (const float*)d_in[1];
    const void*  gty = d_in[2];
    (void)in_sizes; (void)n_in; (void)out_size;

    mls_fused<<<NB, NT>>>(muX, lss, gty, (float*)d_out);
}

// round 8
// speedup vs baseline: 1.2067x; 1.2067x over previous
#include <cuda_runtime.h>

#define N 768
#define D 512
#define MAXP ((N * (N - 1)) / 2)
#define B2 592
#define T2 256
#define NW2 (B2 * T2 / 32)            // 4736 warps in K2

// Scratch (no allocations allowed anywhere). Zero-initialized at load.
__device__ float  g_mu[N * D];
__device__ float  g_sig[N * D];
__device__ int    g_pairs[MAXP];
__device__ double g_part[B2];
__device__ int    g_cnt;              // reset by K2's last-done block
__device__ int    g_done;

__device__ __forceinline__ float fast_rcp(float x) {
    float r; asm("rcp.approx.f32 %0, %1;" : "=f"(r) : "f"(x)); return r;
}
__device__ __forceinline__ float fast_lg2(float x) {
    float r; asm("lg2.approx.f32 %0, %1;" : "=f"(r) : "f"(x)); return r;
}

// ---------------------------------------------------------------------------
// K1: per-row normalize + exp + pair generation.
//     One block per row, 128 threads. Pair compaction happens in shared
//     memory; exactly ONE global atomic per block claims the output slice.
// ---------------------------------------------------------------------------
__global__ void __launch_bounds__(128)
prep_kernel(const float* __restrict__ muX,
            const float* __restrict__ lss,
            const void*  __restrict__ gty) {
    __shared__ float ws[4];
    __shared__ int   s_n;
    __shared__ int   s_base;
    __shared__ int   s_list[N];

    int row = blockIdx.x;
    int t   = threadIdx.x;
    int lane = t & 31;
    int wid  = t >> 5;

    // ---- mu row sum-of-squares ----
    float4 v = ((const float4*)(muX + (size_t)row * D))[t];
    float ss = v.x * v.x + v.y * v.y + v.z * v.z + v.w * v.w;
    #pragma unroll
    for (int o = 16; o; o >>= 1) ss += __shfl_xor_sync(0xFFFFFFFFu, ss, o);
    if (lane == 0) ws[wid] = ss;
    if (t == 0) s_n = 0;

    // ---- label width detection (int64 vs int32) ----
    // Values in [0,64). If little-endian int64, odd 32-bit words of the first
    // N words are all 0. Word index 2*j <= 1534 is in-bounds for int64 layout.
    const int* gw = (const int*)gty;
    int flag = 0;
    #pragma unroll
    for (int k = 0; k < 6; k++) {
        int x = t + (k << 7);
        if ((x & 1) && gw[x] != 0) flag = 1;
    }
    int is32 = __syncthreads_or(flag);

    // ---- normalize + exp, write staging rows ----
    float total = ws[0] + ws[1] + ws[2] + ws[3];
    float rn = 1.0f / fmaxf(sqrtf(total), 1e-12f);
    ((float4*)(g_mu + (size_t)row * D))[t] =
        make_float4(v.x * rn, v.y * rn, v.z * rn, v.w * rn);
    float4 l = ((const float4*)(lss + (size_t)row * D))[t];
    ((float4*)(g_sig + (size_t)row * D))[t] =
        make_float4(__expf(l.x), __expf(l.y), __expf(l.z), __expf(l.w));

    // ---- pairgen into shared list (smem atomics only) ----
    int li = is32 ? gw[row] : gw[2 * row];
    #pragma unroll
    for (int k = 0; k < 6; k++) {
        int j = t + (k << 7);
        if (j > row && (is32 ? gw[j] : gw[2 * j]) == li)
            s_list[atomicAdd(&s_n, 1)] = (row << 16) | j;
    }
    __syncthreads();
    if (t == 0) s_base = s_n ? atomicAdd(&g_cnt, s_n) : 0;
    __syncthreads();
    for (int p = t; p < s_n; p += 128)
        g_pairs[s_base + p] = s_list[p];
}

// ---------------------------------------------------------------------------
// K2: one warp per pair (R1's fast config), grouped lg2, folded finish.
// ---------------------------------------------------------------------------
__global__ void __launch_bounds__(T2)
mls_kernel(float* __restrict__ out) {
    __shared__ double wsum[T2 / 32];
    __shared__ int    sh_last;

    int t    = threadIdx.x;
    int lane = t & 31;
    int wid  = t >> 5;
    int gwarp = blockIdx.x * (T2 / 32) + wid;
    int np = g_cnt;

    float accd = 0.0f;   // sum of d^2 * rcp(s)
    float accl = 0.0f;   // sum of lg2(prod of s)
    for (int p = gwarp; p < np; p += NW2) {
        int pk = g_pairs[p];
        int pi = pk >> 16;
        int pj = pk & 0xFFFF;
        const float4* mi = (const float4*)(g_mu  + (size_t)pi * D);
        const float4* mj = (const float4*)(g_mu  + (size_t)pj * D);
        const float4* si = (const float4*)(g_sig + (size_t)pi * D);
        const float4* sj = (const float4*)(g_sig + (size_t)pj * D);
        #pragma unroll
        for (int k = 0; k < 4; k++) {
            int idx = lane + 32 * k;      // 128 float4 per row
            float4 a = mi[idx], b = mj[idx];
            float4 u = si[idx], v = sj[idx];
            float d, s, prod;
            d = a.x - b.x; s = u.x + v.x + 1e-10f;
            accd += d * d * fast_rcp(s); prod = s;
            d = a.y - b.y; s = u.y + v.y + 1e-10f;
            accd += d * d * fast_rcp(s); prod *= s;
            d = a.z - b.z; s = u.z + v.z + 1e-10f;
            accd += d * d * fast_rcp(s); prod *= s;
            d = a.w - b.w; s = u.w + v.w + 1e-10f;
            accd += d * d * fast_rcp(s); prod *= s;
            accl += fast_lg2(prod);       // 1 lg2 per 4 elements
        }
    }

    // warp reduce (float), block reduce (double)
    float val = accd + 0.69314718055994531f * accl;
    #pragma unroll
    for (int o = 16; o; o >>= 1) val += __shfl_xor_sync(0xFFFFFFFFu, val, o);
    if (lane == 0) wsum[wid] = (double)val;
    __syncthreads();
    if (t == 0) {
        double bs = 0.0;
        #pragma unroll
        for (int w = 0; w < T2 / 32; w++) bs += wsum[w];
        g_part[blockIdx.x] = bs;
        __threadfence();
        sh_last = (atomicAdd(&g_done, 1) == B2 - 1) ? 1 : 0;
    }
    __syncthreads();

    // last-done block: deterministic final reduction + counter resets
    if (sh_last) {
        double a2 = 0.0;
        for (int i = t; i < B2; i += T2)
            a2 += __ldcg(&g_part[i]);
        #pragma unroll
        for (int o = 16; o; o >>= 1) a2 += __shfl_xor_sync(0xFFFFFFFFu, a2, o);
        if (lane == 0) wsum[wid] = a2;
        __syncthreads();
        if (t == 0) {
            double s = 0.0;
            #pragma unroll
            for (int w = 0; w < T2 / 32; w++) s += wsum[w];
            out[0] = np ? (float)(s / (double)np) : 0.0f;
            g_done = 0;                  // reset for next graph replay
            g_cnt  = 0;
        }
    }
}

extern "C" void kernel_launch(void* const* d_in, const int* in_sizes, int n_in,
                              void* d_out, int out_size) {
    const float* muX = (const float*)d_in[0];
    const float* lss = (const float*)d_in[1];
    const void*  gty = d_in[2];
    (void)in_sizes; (void)n_in; (void)out_size;

    prep_kernel<<<N, 128>>>(muX, lss, gty);
    mls_kernel<<<B2, T2>>>((float*)d_out);
}

// round 9
// speedup vs baseline: 1.2121x; 1.0045x over previous
#include <cuda_runtime.h>

#define N 768
#define D 512
#define MAXP ((N * (N - 1)) / 2)
#define B2 592
#define T2 256
#define NW2 (B2 * T2 / 32)            // 4736 warps in K2

// Scratch (no allocations allowed anywhere). Zero-initialized at load.
__device__ float  g_mu[N * D];
__device__ float  g_sig[N * D];
__device__ int    g_pairs[MAXP];
__device__ double g_part[B2];
__device__ int    g_cnt;              // reset by K2's poller block
__device__ int    g_done;

__device__ __forceinline__ float fast_rcp(float x) {
    float r; asm("rcp.approx.f32 %0, %1;" : "=f"(r) : "f"(x)); return r;
}
__device__ __forceinline__ float fast_lg2(float x) {
    float r; asm("lg2.approx.f32 %0, %1;" : "=f"(r) : "f"(x)); return r;
}

// ---------------------------------------------------------------------------
// K1: per-row normalize + exp + pair generation.
//     One block per row, 128 threads. Pair compaction happens in shared
//     memory; exactly ONE global atomic per block claims the output slice.
// ---------------------------------------------------------------------------
__global__ void __launch_bounds__(128)
prep_kernel(const float* __restrict__ muX,
            const float* __restrict__ lss,
            const void*  __restrict__ gty) {
    __shared__ float ws[4];
    __shared__ int   s_n;
    __shared__ int   s_base;
    __shared__ int   s_list[N];

    int row = blockIdx.x;
    int t   = threadIdx.x;
    int lane = t & 31;
    int wid  = t >> 5;

    // ---- mu row sum-of-squares ----
    float4 v = ((const float4*)(muX + (size_t)row * D))[t];
    float ss = v.x * v.x + v.y * v.y + v.z * v.z + v.w * v.w;
    #pragma unroll
    for (int o = 16; o; o >>= 1) ss += __shfl_xor_sync(0xFFFFFFFFu, ss, o);
    if (lane == 0) ws[wid] = ss;
    if (t == 0) s_n = 0;

    // ---- label width detection (int64 vs int32) ----
    // Values in [0,64). If little-endian int64, odd 32-bit words of the first
    // N words are all 0. Word index 2*j <= 1534 is in-bounds for int64 layout.
    const int* gw = (const int*)gty;
    int flag = 0;
    #pragma unroll
    for (int k = 0; k < 6; k++) {
        int x = t + (k << 7);
        if ((x & 1) && gw[x] != 0) flag = 1;
    }
    int is32 = __syncthreads_or(flag);

    // ---- normalize + exp, write staging rows ----
    float total = ws[0] + ws[1] + ws[2] + ws[3];
    float rn = 1.0f / fmaxf(sqrtf(total), 1e-12f);
    ((float4*)(g_mu + (size_t)row * D))[t] =
        make_float4(v.x * rn, v.y * rn, v.z * rn, v.w * rn);
    float4 l = ((const float4*)(lss + (size_t)row * D))[t];
    ((float4*)(g_sig + (size_t)row * D))[t] =
        make_float4(__expf(l.x), __expf(l.y), __expf(l.z), __expf(l.w));

    // ---- pairgen into shared list (smem atomics only) ----
    int li = is32 ? gw[row] : gw[2 * row];
    #pragma unroll
    for (int k = 0; k < 6; k++) {
        int j = t + (k << 7);
        if (j > row && (is32 ? gw[j] : gw[2 * j]) == li)
            s_list[atomicAdd(&s_n, 1)] = (row << 16) | j;
    }
    __syncthreads();
    if (t == 0) s_base = s_n ? atomicAdd(&g_cnt, s_n) : 0;
    __syncthreads();
    for (int p = t; p < s_n; p += 128)
        g_pairs[s_base + p] = s_list[p];
}

// ---------------------------------------------------------------------------
// K2: one warp per pair; grouped lg2; cheap release-tail + poller finish.
// ---------------------------------------------------------------------------
__global__ void __launch_bounds__(T2, 4)
mls_kernel(float* __restrict__ out) {
    __shared__ double wsum[T2 / 32];

    int t    = threadIdx.x;
    int lane = t & 31;
    int wid  = t >> 5;
    int gwarp = blockIdx.x * (T2 / 32) + wid;
    int np = g_cnt;

    float accd = 0.0f;   // sum of d^2 * rcp(s)
    float accl = 0.0f;   // sum of lg2(prod of s)
    for (int p = gwarp; p < np; p += NW2) {
        int pk = g_pairs[p];
        int pi = pk >> 16;
        int pj = pk & 0xFFFF;
        const float4* mi = (const float4*)(g_mu  + (size_t)pi * D);
        const float4* mj = (const float4*)(g_mu  + (size_t)pj * D);
        const float4* si = (const float4*)(g_sig + (size_t)pi * D);
        const float4* sj = (const float4*)(g_sig + (size_t)pj * D);
        #pragma unroll
        for (int k = 0; k < 4; k++) {
            int idx = lane + 32 * k;      // 128 float4 per row
            float4 a = mi[idx], b = mj[idx];
            float4 u = si[idx], v = sj[idx];
            float d, s, prod;
            d = a.x - b.x; s = u.x + v.x + 1e-10f;
            accd += d * d * fast_rcp(s); prod = s;
            d = a.y - b.y; s = u.y + v.y + 1e-10f;
            accd += d * d * fast_rcp(s); prod *= s;
            d = a.z - b.z; s = u.z + v.z + 1e-10f;
            accd += d * d * fast_rcp(s); prod *= s;
            d = a.w - b.w; s = u.w + v.w + 1e-10f;
            accd += d * d * fast_rcp(s); prod *= s;
            accl += fast_lg2(prod);       // 1 lg2 per 4 elements
        }
    }

    // warp reduce (float), block reduce (double)
    float val = accd + 0.69314718055994531f * accl;
    #pragma unroll
    for (int o = 16; o; o >>= 1) val += __shfl_xor_sync(0xFFFFFFFFu, val, o);
    if (lane == 0) wsum[wid] = (double)val;
    __syncthreads();
    if (t == 0) {
        double bs = 0.0;
        #pragma unroll
        for (int w = 0; w < T2 / 32; w++) bs += wsum[w];
        g_part[blockIdx.x] = bs;
        // fire-and-forget arrival; release orders the partial store above
        asm volatile("red.release.gpu.global.add.s32 [%0], %1;"
                     :: "l"(&g_done), "r"(1) : "memory");
    }

    // Poller block: waits for all arrivals, does deterministic final reduce.
    if (blockIdx.x == B2 - 1) {
        if (t == 0) {
            int c;
            do {
                asm volatile("ld.acquire.gpu.global.s32 %0, [%1];"
                             : "=r"(c) : "l"(&g_done) : "memory");
                if (c < B2) __nanosleep(32);
            } while (c < B2);
        }
        __syncthreads();

        double a2 = 0.0;
        for (int i = t; i < B2; i += T2)
            a2 += __ldcg(&g_part[i]);
        #pragma unroll
        for (int o = 16; o; o >>= 1) a2 += __shfl_xor_sync(0xFFFFFFFFu, a2, o);
        if (lane == 0) wsum[wid] = a2;
        __syncthreads();
        if (t == 0) {
            double s = 0.0;
            #pragma unroll
            for (int w = 0; w < T2 / 32; w++) s += wsum[w];
            out[0] = np ? (float)(s / (double)np) : 0.0f;
            g_done = 0;                  // reset for next graph replay
            g_cnt  = 0;
        }
    }
}

extern "C" void kernel_launch(void* const* d_in, const int* in_sizes, int n_in,
                              void* d_out, int out_size) {
    const float* muX = (const float*)d_in[0];
    const float* lss = (const float*)d_in[1];
    const void*  gty = d_in[2];
    (void)in_sizes; (void)n_in; (void)out_size;

    prep_kernel<<<N, 128>>>(muX, lss, gty);
    mls_kernel<<<B2, T2>>>((float*)d_out);
}

// round 11
// speedup vs baseline: 1.2230x; 1.0090x over previous
#include <cuda_runtime.h>

#define N 768
#define D 512
#define MAXP ((N * (N - 1)) / 2)
#define B2 592
#define T2 256
#define NW2 (B2 * T2 / 32)            // 4736 warps in K2

// Scratch (no allocations allowed anywhere). Zero-initialized at load.
__device__ float  g_mu[N * D];
__device__ float  g_sig[N * D];
__device__ int    g_pairs[MAXP];
__device__ double g_part[B2];
__device__ int    g_cnt;              // reset by K2's poller block
__device__ int    g_done;

__device__ __forceinline__ float fast_rcp(float x) {
    float r; asm("rcp.approx.f32 %0, %1;" : "=f"(r) : "f"(x)); return r;
}
__device__ __forceinline__ float fast_lg2(float x) {
    float r; asm("lg2.approx.f32 %0, %1;" : "=f"(r) : "f"(x)); return r;
}

// ---------------------------------------------------------------------------
// K1: per-row normalize + exp + pair generation.
//     One block per row, 128 threads. Pair compaction happens in shared
//     memory; exactly ONE global atomic per block claims the output slice.
//     Triggers PDL immediately so K2's grid ramps up concurrently.
// ---------------------------------------------------------------------------
__global__ void __launch_bounds__(128)
prep_kernel(const float* __restrict__ muX,
            const float* __restrict__ lss,
            const void*  __restrict__ gty) {
    cudaTriggerProgrammaticLaunchCompletion();   // let K2 start spinning up

    __shared__ float ws[4];
    __shared__ int   s_n;
    __shared__ int   s_base;
    __shared__ int   s_list[N];

    int row = blockIdx.x;
    int t   = threadIdx.x;
    int lane = t & 31;
    int wid  = t >> 5;

    // ---- mu row sum-of-squares ----
    float4 v = ((const float4*)(muX + (size_t)row * D))[t];
    float ss = v.x * v.x + v.y * v.y + v.z * v.z + v.w * v.w;
    #pragma unroll
    for (int o = 16; o; o >>= 1) ss += __shfl_xor_sync(0xFFFFFFFFu, ss, o);
    if (lane == 0) ws[wid] = ss;
    if (t == 0) s_n = 0;

    // ---- label width detection (int64 vs int32) ----
    // Values in [0,64). If little-endian int64, odd 32-bit words of the first
    // N words are all 0. Word index 2*j <= 1534 is in-bounds for int64 layout.
    const int* gw = (const int*)gty;
    int flag = 0;
    #pragma unroll
    for (int k = 0; k < 6; k++) {
        int x = t + (k << 7);
        if ((x & 1) && gw[x] != 0) flag = 1;
    }
    int is32 = __syncthreads_or(flag);

    // ---- normalize + exp, write staging rows ----
    float total = ws[0] + ws[1] + ws[2] + ws[3];
    float rn = 1.0f / fmaxf(sqrtf(total), 1e-12f);
    ((float4*)(g_mu + (size_t)row * D))[t] =
        make_float4(v.x * rn, v.y * rn, v.z * rn, v.w * rn);
    float4 l = ((const float4*)(lss + (size_t)row * D))[t];
    ((float4*)(g_sig + (size_t)row * D))[t] =
        make_float4(__expf(l.x), __expf(l.y), __expf(l.z), __expf(l.w));

    // ---- pairgen into shared list (smem atomics only) ----
    int li = is32 ? gw[row] : gw[2 * row];
    #pragma unroll
    for (int k = 0; k < 6; k++) {
        int j = t + (k << 7);
        if (j > row && (is32 ? gw[j] : gw[2 * j]) == li)
            s_list[atomicAdd(&s_n, 1)] = (row << 16) | j;
    }
    __syncthreads();
    if (t == 0) s_base = s_n ? atomicAdd(&g_cnt, s_n) : 0;
    __syncthreads();
    for (int p = t; p < s_n; p += 128)
        g_pairs[s_base + p] = s_list[p];
}

// ---------------------------------------------------------------------------
// K2: one warp per pair; grouped lg2; cheap release-tail + poller finish.
//     Waits on the PDL grid dependency before reading K1's outputs.
// ---------------------------------------------------------------------------
__global__ void __launch_bounds__(T2, 4)
mls_kernel(float* __restrict__ out) {
    __shared__ double wsum[T2 / 32];

    int t    = threadIdx.x;
    int lane = t & 31;
    int wid  = t >> 5;
    int gwarp = blockIdx.x * (T2 / 32) + wid;

    cudaGridDependencySynchronize();   // no-op if PDL wasn't used

    int np = g_cnt;

    float accd = 0.0f;   // sum of d^2 * rcp(s)
    float accl = 0.0f;   // sum of lg2(prod of s)
    for (int p = gwarp; p < np; p += NW2) {
        int pk = g_pairs[p];
        int pi = pk >> 16;
        int pj = pk & 0xFFFF;
        const float4* mi = (const float4*)(g_mu  + (size_t)pi * D);
        const float4* mj = (const float4*)(g_mu  + (size_t)pj * D);
        const float4* si = (const float4*)(g_sig + (size_t)pi * D);
        const float4* sj = (const float4*)(g_sig + (size_t)pj * D);
        #pragma unroll
        for (int k = 0; k < 4; k++) {
            int idx = lane + 32 * k;      // 128 float4 per row
            float4 a = mi[idx], b = mj[idx];
            float4 u = si[idx], v = sj[idx];
            float d, s, prod;
            d = a.x - b.x; s = u.x + v.x;
            accd += d * d * fast_rcp(s); prod = s;
            d = a.y - b.y; s = u.y + v.y;
            accd += d * d * fast_rcp(s); prod *= s;
            d = a.z - b.z; s = u.z + v.z;
            accd += d * d * fast_rcp(s); prod *= s;
            d = a.w - b.w; s = u.w + v.w;
            accd += d * d * fast_rcp(s); prod *= s;
            accl += fast_lg2(prod);       // 1 lg2 per 4 elements
        }
    }

    // warp reduce (float), block reduce (double)
    float val = accd + 0.69314718055994531f * accl;
    #pragma unroll
    for (int o = 16; o; o >>= 1) val += __shfl_xor_sync(0xFFFFFFFFu, val, o);
    if (lane == 0) wsum[wid] = (double)val;
    __syncthreads();
    if (t == 0) {
        double bs = 0.0;
        #pragma unroll
        for (int w = 0; w < T2 / 32; w++) bs += wsum[w];
        g_part[blockIdx.x] = bs;
        // fire-and-forget arrival; release orders the partial store above
        asm volatile("red.release.gpu.global.add.s32 [%0], %1;"
                     :: "l"(&g_done), "r"(1) : "memory");
    }

    // Poller block: waits for all arrivals, does deterministic final reduce.
    if (blockIdx.x == B2 - 1) {
        if (t == 0) {
            int c;
            do {
                asm volatile("ld.acquire.gpu.global.s32 %0, [%1];"
                             : "=r"(c) : "l"(&g_done) : "memory");
                if (c < B2) __nanosleep(32);
            } while (c < B2);
        }
        __syncthreads();

        double a2 = 0.0;
        for (int i = t; i < B2; i += T2)
            a2 += __ldcg(&g_part[i]);
        #pragma unroll
        for (int o = 16; o; o >>= 1) a2 += __shfl_xor_sync(0xFFFFFFFFu, a2, o);
        if (lane == 0) wsum[wid] = a2;
        __syncthreads();
        if (t == 0) {
            double s = 0.0;
            #pragma unroll
            for (int w = 0; w < T2 / 32; w++) s += wsum[w];
            out[0] = np ? (float)(s / (double)np) : 0.0f;
            g_done = 0;                  // reset for next graph replay
            g_cnt  = 0;
        }
    }
}

extern "C" void kernel_launch(void* const* d_in, const int* in_sizes, int n_in,
                              void* d_out, int out_size) {
    const float* muX = (const float*)d_in[0];
    const float* lss = (const float*)d_in[1];
    const void*  gty = d_in[2];
    (void)in_sizes; (void)n_in; (void)out_size;

    prep_kernel<<<N, 128>>>(muX, lss, gty);

    // K2 with Programmatic Dependent Launch; fall back to a plain launch if
    // the attribute/Ex path is rejected (e.g. unsupported under capture).
    cudaLaunchConfig_t cfg = {};
    cfg.gridDim  = dim3(B2, 1, 1);
    cfg.blockDim = dim3(T2, 1, 1);
    cfg.dynamicSmemBytes = 0;
    cfg.stream = 0;
    cudaLaunchAttribute attr[1];
    attr[0].id = cudaLaunchAttributeProgrammaticStreamSerialization;
    attr[0].val.programmaticStreamSerializationAllowed = 1;
    cfg.attrs = attr;
    cfg.numAttrs = 1;
    float* outp = (float*)d_out;
    if (cudaLaunchKernelEx(&cfg, mls_kernel, outp) != cudaSuccess) {
        mls_kernel<<<B2, T2>>>(outp);
    }
}